// round 4
// baseline (speedup 1.0000x reference)
#include <cuda_runtime.h>
#include <math.h>
#include <stdint.h>

#define NN   50000
#define EE   800000
#define EE2  (EE + NN)        // 850000 edges incl self-loops
#define BETA_C  0.04879016416943205f   // log(0.1/2 + 1)

// ---------------- device scratch (static; no allocation allowed) ----------------
__device__ __align__(16) float g_bufA[NN * 256];
__device__ __align__(16) float g_bufB[NN * 256];
__device__ __align__(16) float g_bufC[NN * 256];
__device__ __align__(16) float g_X1[NN * 256];
__device__ __align__(16) float g_X2[NN * 128];
__device__ float g_dinv[NN];
__device__ int   g_cnt[NN];
__device__ int   g_rowptr[NN + 1];
__device__ int   g_src[EE];
__device__ int   g_dst[EE];
__device__ int   g_csr_src[EE2];
__device__ float g_csr_norm[EE2];
__device__ __align__(16) float g_alog[EE2 * 4];
__device__ int   g_part[64];
__device__ int   g_is64;

// ---------------- edge dtype detection & conversion ----------------
__global__ void k_detect(const int* __restrict__ ei) {
    if (threadIdx.x == 0 && blockIdx.x == 0) {
        int flag64 = 1;
        for (int i = 1; i < 2048; i += 2) {
            if (ei[i] != 0) { flag64 = 0; break; }
        }
        g_is64 = flag64;
    }
}

__global__ void k_convert(const void* __restrict__ ei) {
    int e = blockIdx.x * 256 + threadIdx.x;
    if (e >= EE) return;
    if (g_is64) {
        const long long* p = (const long long*)ei;
        g_src[e] = (int)p[e];
        g_dst[e] = (int)p[EE + e];
    } else {
        const int* p = (const int*)ei;
        g_src[e] = p[e];
        g_dst[e] = p[EE + e];
    }
}

// ---------------- degree / norm / CSR build ----------------
__global__ void k_init_cnt() {
    int i = blockIdx.x * 256 + threadIdx.x;
    if (i < NN) g_cnt[i] = 1;   // self-loop contributes 1 to in-degree
}

__global__ void k_count() {
    int e = blockIdx.x * 256 + threadIdx.x;
    if (e < EE) atomicAdd(&g_cnt[g_dst[e]], 1);
}

__global__ void k_dinv() {
    int i = blockIdx.x * 256 + threadIdx.x;
    if (i < NN) {
        float d = (float)g_cnt[i];
        g_dinv[i] = (d > 0.f) ? rsqrtf(d) : 0.f;
    }
}

// exclusive scan of g_cnt -> g_rowptr (three-phase)
__global__ void k_scan1() {
    __shared__ int sh[1024];
    int i = blockIdx.x * 1024 + threadIdx.x;
    int v = (i < NN) ? g_cnt[i] : 0;
    sh[threadIdx.x] = v;
    __syncthreads();
    for (int off = 1; off < 1024; off <<= 1) {
        int t = (threadIdx.x >= off) ? sh[threadIdx.x - off] : 0;
        __syncthreads();
        sh[threadIdx.x] += t;
        __syncthreads();
    }
    if (i < NN) g_rowptr[i] = sh[threadIdx.x] - v;   // exclusive
    if (threadIdx.x == 1023) g_part[blockIdx.x] = sh[1023];
}

__global__ void k_scan2(int nblk) {
    if (threadIdx.x == 0 && blockIdx.x == 0) {
        int acc = 0;
        for (int b = 0; b < nblk; b++) { int t = g_part[b]; g_part[b] = acc; acc += t; }
    }
}

__global__ void k_scan3() {
    int i = blockIdx.x * 1024 + threadIdx.x;
    if (i < NN) {
        g_rowptr[i] += g_part[blockIdx.x];
        g_cnt[i] = 0;    // reuse as fill cursor
    }
    if (i == 0) g_rowptr[NN] = EE2;
}

__global__ void k_fill() {
    int e = blockIdx.x * 256 + threadIdx.x;
    if (e >= EE2) return;
    int s, d;
    if (e < EE) { s = g_src[e]; d = g_dst[e]; }
    else        { s = d = e - EE; }
    float nrm = g_dinv[s] * g_dinv[d];
    int pos = g_rowptr[d] + atomicAdd(&g_cnt[d], 1);
    g_csr_src[pos] = s;
    g_csr_norm[pos] = nrm;
}

// ---------------- fp32 tiled GEMM 64x64 (small-N fallback) ----------------
__global__ void k_gemm(const float* __restrict__ A, const float* __restrict__ W,
                       float* __restrict__ C, int M, int K, int Ncol) {
    __shared__ float As[64][17];
    __shared__ float Ws[16][64];
    int tx = threadIdx.x & 15, ty = threadIdx.x >> 4;
    int rb = blockIdx.y * 64, cb = blockIdx.x * 64;
    float acc[4][4] = {};

    for (int k0 = 0; k0 < K; k0 += 16) {
#pragma unroll
        for (int l = 0; l < 4; l++) {
            int lin = threadIdx.x + l * 256;
            int m = lin >> 4, kk = lin & 15;
            int gr = rb + m, gk = k0 + kk;
            As[m][kk] = (gr < M && gk < K) ? A[(size_t)gr * K + gk] : 0.f;
        }
#pragma unroll
        for (int l = 0; l < 4; l++) {
            int lin = threadIdx.x + l * 256;
            int kk = lin >> 6, n = lin & 63;
            int gk = k0 + kk, gc = cb + n;
            Ws[kk][n] = (gk < K && gc < Ncol) ? W[(size_t)gk * Ncol + gc] : 0.f;
        }
        __syncthreads();
#pragma unroll
        for (int kk = 0; kk < 16; kk++) {
            float a[4], b[4];
#pragma unroll
            for (int i = 0; i < 4; i++) a[i] = As[ty + i * 16][kk];
#pragma unroll
            for (int j = 0; j < 4; j++) b[j] = Ws[kk][tx + j * 16];
#pragma unroll
            for (int i = 0; i < 4; i++)
#pragma unroll
                for (int j = 0; j < 4; j++) acc[i][j] += a[i] * b[j];
        }
        __syncthreads();
    }
#pragma unroll
    for (int i = 0; i < 4; i++) {
        int r = rb + ty + i * 16;
        if (r >= M) continue;
#pragma unroll
        for (int j = 0; j < 4; j++) {
            int c = cb + tx + j * 16;
            if (c < Ncol) C[(size_t)r * Ncol + c] = acc[i][j];
        }
    }
}

// ---------------- fp32 SGEMM 128x128x8, 8x8/thread, double-buffered smem ----------------
__global__ void __launch_bounds__(256, 2)
k_gemm128(const float* __restrict__ A, const float* __restrict__ W,
          float* __restrict__ C, int M, int K, int Ncol) {
    __shared__ float As[2][8][132];   // transposed A slab; pitch 132 -> conflict-free, 16B-aligned rows
    __shared__ float Ws[2][8][128];
    int tid = threadIdx.x;
    int tx = tid & 15, ty = tid >> 4;
    int rb = blockIdx.y * 128, cb = blockIdx.x * 128;
    float acc[8][8] = {};

    // per-thread staging indices (4 A elems + 4 W elems per tile)
    int amRow[4], akCol[4], wkRow[4], wnCol[4];
#pragma unroll
    for (int i = 0; i < 4; i++) {
        int idx = tid + i * 256;
        amRow[i] = idx >> 3;  akCol[i] = idx & 7;     // A tile: 128 rows x 8 k
        wkRow[i] = idx >> 7;  wnCol[i] = idx & 127;   // W tile: 8 k x 128 n
    }

    // preload tile 0 into buffer 0
#pragma unroll
    for (int i = 0; i < 4; i++) {
        int gr = rb + amRow[i], gk = akCol[i];
        As[0][akCol[i]][amRow[i]] = (gr < M && gk < K) ? A[(size_t)gr * K + gk] : 0.f;
        int gk2 = wkRow[i], gc = cb + wnCol[i];
        Ws[0][wkRow[i]][wnCol[i]] = (gk2 < K && gc < Ncol) ? W[(size_t)gk2 * Ncol + gc] : 0.f;
    }
    __syncthreads();

    int nTiles = (K + 7) >> 3;
    for (int t = 0; t < nTiles; t++) {
        int cur = t & 1, nxt = cur ^ 1;
        float ra[4], rw[4];
        if (t + 1 < nTiles) {
            int k0 = (t + 1) << 3;
#pragma unroll
            for (int i = 0; i < 4; i++) {
                int gr = rb + amRow[i], gk = k0 + akCol[i];
                ra[i] = (gr < M && gk < K) ? A[(size_t)gr * K + gk] : 0.f;
                int gk2 = k0 + wkRow[i], gc = cb + wnCol[i];
                rw[i] = (gk2 < K && gc < Ncol) ? W[(size_t)gk2 * Ncol + gc] : 0.f;
            }
        }
#pragma unroll
        for (int kk = 0; kk < 8; kk++) {
            float4 a0 = *(const float4*)&As[cur][kk][ty * 4];
            float4 a1 = *(const float4*)&As[cur][kk][ty * 4 + 64];
            float4 b0 = *(const float4*)&Ws[cur][kk][tx * 4];
            float4 b1 = *(const float4*)&Ws[cur][kk][tx * 4 + 64];
            float av[8] = {a0.x, a0.y, a0.z, a0.w, a1.x, a1.y, a1.z, a1.w};
            float bv[8] = {b0.x, b0.y, b0.z, b0.w, b1.x, b1.y, b1.z, b1.w};
#pragma unroll
            for (int i = 0; i < 8; i++)
#pragma unroll
                for (int j = 0; j < 8; j++) acc[i][j] += av[i] * bv[j];
        }
        if (t + 1 < nTiles) {
#pragma unroll
            for (int i = 0; i < 4; i++) {
                As[nxt][akCol[i]][amRow[i]] = ra[i];
                Ws[nxt][wkRow[i]][wnCol[i]] = rw[i];
            }
            __syncthreads();
        }
    }
#pragma unroll
    for (int i = 0; i < 8; i++) {
        int r = rb + ty * 4 + ((i < 4) ? i : (64 + i - 4));
        if (r >= M) continue;
#pragma unroll
        for (int j = 0; j < 8; j++) {
            int c = cb + tx * 4 + ((j < 4) ? j : (64 + j - 4));
            if (c < Ncol) C[(size_t)r * Ncol + c] = acc[i][j];
        }
    }
}

// ---------------- CSR gather-propagation (scalar, D = C*32) ----------------
// MODE 0: relu(acc+bias)   MODE 1: acc+bias   MODE 2: 0.5*acc + 0.5*X0
template <int C, int MODE>
__global__ void k_prop(const float* __restrict__ H, float* __restrict__ Out,
                       const float* __restrict__ bias, const float* __restrict__ X0) {
    int warp = threadIdx.x >> 5, lane = threadIdx.x & 31;
    int node = blockIdx.x * 8 + warp;
    if (node >= NN) return;
    const int D = C * 32;
    int rs = g_rowptr[node], re = g_rowptr[node + 1];
    float acc[C];
#pragma unroll
    for (int c = 0; c < C; c++) acc[c] = 0.f;

#pragma unroll 4
    for (int k = rs; k < re; k++) {
        int s = g_csr_src[k];
        float w = g_csr_norm[k];
        const float* hp = H + (size_t)s * D + lane;
#pragma unroll
        for (int c = 0; c < C; c++) acc[c] += w * __ldg(hp + 32 * c);
    }
    float* op = Out + (size_t)node * D + lane;
#pragma unroll
    for (int c = 0; c < C; c++) {
        float v = acc[c];
        if (MODE == 0)      { v += bias[lane + 32 * c]; v = fmaxf(v, 0.f); }
        else if (MODE == 1) { v += bias[lane + 32 * c]; }
        else                { v = 0.5f * v + 0.5f * X0[(size_t)node * D + lane + 32 * c]; }
        op[32 * c] = v;
    }
}

// ---------------- CSR gather-propagation (float4, D = C4*128) ----------------
template <int C4, int MODE>
__global__ void k_prop4(const float4* __restrict__ H4, float4* __restrict__ Out4,
                        const float4* __restrict__ bias4, const float4* __restrict__ X04) {
    int warp = threadIdx.x >> 5, lane = threadIdx.x & 31;
    int node = blockIdx.x * 8 + warp;
    if (node >= NN) return;
    const int D4 = C4 * 32;            // float4s per row
    int rs = g_rowptr[node], re = g_rowptr[node + 1];
    float4 acc[C4];
#pragma unroll
    for (int c = 0; c < C4; c++) acc[c] = make_float4(0.f, 0.f, 0.f, 0.f);

#pragma unroll 4
    for (int k = rs; k < re; k++) {
        int s = g_csr_src[k];
        float w = g_csr_norm[k];
        const float4* hp = H4 + (size_t)s * D4 + lane;
#pragma unroll
        for (int c = 0; c < C4; c++) {
            float4 v = __ldg(hp + 32 * c);
            acc[c].x += w * v.x; acc[c].y += w * v.y;
            acc[c].z += w * v.z; acc[c].w += w * v.w;
        }
    }
    float4* op = Out4 + (size_t)node * D4 + lane;
#pragma unroll
    for (int c = 0; c < C4; c++) {
        float4 v = acc[c];
        if (MODE == 0) {
            float4 b = bias4[lane + 32 * c];
            v.x = fmaxf(v.x + b.x, 0.f); v.y = fmaxf(v.y + b.y, 0.f);
            v.z = fmaxf(v.z + b.z, 0.f); v.w = fmaxf(v.w + b.w, 0.f);
        } else if (MODE == 1) {
            float4 b = bias4[lane + 32 * c];
            v.x += b.x; v.y += b.y; v.z += b.z; v.w += b.w;
        } else {
            float4 x0 = X04[(size_t)node * D4 + lane + 32 * c];
            v.x = 0.5f * v.x + 0.5f * x0.x; v.y = 0.5f * v.y + 0.5f * x0.y;
            v.z = 0.5f * v.z + 0.5f * x0.z; v.w = 0.5f * v.w + 0.5f * x0.w;
        }
        op[32 * c] = v;
    }
}

// ---------------- GATv2 ----------------
// per-edge logits: a[e][h] = sum_c att[h][c]*leaky_relu(xl[src][h,c] + xr[dst][h,c])
__global__ void k_gat_logits(const float4* __restrict__ XL4, const float4* __restrict__ XR4,
                             const float* __restrict__ att) {
    int warp = threadIdx.x >> 5, lane = threadIdx.x & 31;
    int node = blockIdx.x * 8 + warp;
    if (node >= NN) return;
    int rs = g_rowptr[node], re = g_rowptr[node + 1];
    float4 xr = XR4[(size_t)node * 32 + lane];
    float4 at = ((const float4*)att)[lane];

#pragma unroll 2
    for (int pos = rs; pos < re; pos++) {
        int s = g_csr_src[pos];
        float4 xl = __ldg(&XL4[(size_t)s * 32 + lane]);
        float v0 = xl.x + xr.x; v0 = v0 > 0.f ? v0 : 0.2f * v0;
        float v1 = xl.y + xr.y; v1 = v1 > 0.f ? v1 : 0.2f * v1;
        float v2 = xl.z + xr.z; v2 = v2 > 0.f ? v2 : 0.2f * v2;
        float v3 = xl.w + xr.w; v3 = v3 > 0.f ? v3 : 0.2f * v3;
        float sum = at.x * v0 + at.y * v1 + at.z * v2 + at.w * v3;
        sum += __shfl_xor_sync(0xFFFFFFFFu, sum, 1);
        sum += __shfl_xor_sync(0xFFFFFFFFu, sum, 2);
        sum += __shfl_xor_sync(0xFFFFFFFFu, sum, 4);
        if ((lane & 7) == 0) g_alog[(size_t)pos * 4 + (lane >> 3)] = sum;
    }
}

// per-node softmax over incoming edges + weighted aggregation of xl[src]
__global__ void k_gat_aggr(const float4* __restrict__ XL4, float4* __restrict__ Out4,
                           const float4* __restrict__ bg4) {
    int warp = threadIdx.x >> 5, lane = threadIdx.x & 31;
    int node = blockIdx.x * 8 + warp;
    if (node >= NN) return;
    int rs = g_rowptr[node], re = g_rowptr[node + 1];
    const float4* AL4 = (const float4*)g_alog;

    float4 mx = make_float4(-1e30f, -1e30f, -1e30f, -1e30f);
    for (int pos = rs + lane; pos < re; pos += 32) {
        float4 a = AL4[pos];
        mx.x = fmaxf(mx.x, a.x); mx.y = fmaxf(mx.y, a.y);
        mx.z = fmaxf(mx.z, a.z); mx.w = fmaxf(mx.w, a.w);
    }
#pragma unroll
    for (int off = 16; off; off >>= 1) {
        mx.x = fmaxf(mx.x, __shfl_xor_sync(0xFFFFFFFFu, mx.x, off));
        mx.y = fmaxf(mx.y, __shfl_xor_sync(0xFFFFFFFFu, mx.y, off));
        mx.z = fmaxf(mx.z, __shfl_xor_sync(0xFFFFFFFFu, mx.z, off));
        mx.w = fmaxf(mx.w, __shfl_xor_sync(0xFFFFFFFFu, mx.w, off));
    }
    float4 se = make_float4(0.f, 0.f, 0.f, 0.f);
    for (int pos = rs + lane; pos < re; pos += 32) {
        float4 a = AL4[pos];
        se.x += __expf(a.x - mx.x); se.y += __expf(a.y - mx.y);
        se.z += __expf(a.z - mx.z); se.w += __expf(a.w - mx.w);
    }
#pragma unroll
    for (int off = 16; off; off >>= 1) {
        se.x += __shfl_xor_sync(0xFFFFFFFFu, se.x, off);
        se.y += __shfl_xor_sync(0xFFFFFFFFu, se.y, off);
        se.z += __shfl_xor_sync(0xFFFFFFFFu, se.z, off);
        se.w += __shfl_xor_sync(0xFFFFFFFFu, se.w, off);
    }
    // this lane covers columns lane*4..lane*4+3 -> single head = lane>>3
    int head = lane >> 3;
    float mxh  = (head == 0) ? mx.x : (head == 1) ? mx.y : (head == 2) ? mx.z : mx.w;
    float seh  = (head == 0) ? se.x : (head == 1) ? se.y : (head == 2) ? se.z : se.w;
    float invh = 1.f / (seh + 1e-16f);

    float4 acc = make_float4(0.f, 0.f, 0.f, 0.f);
#pragma unroll 2
    for (int pos = rs; pos < re; pos++) {
        float4 a = AL4[pos];    // broadcast across warp
        float ah = (head == 0) ? a.x : (head == 1) ? a.y : (head == 2) ? a.z : a.w;
        float w = __expf(ah - mxh) * invh;
        int s = g_csr_src[pos];
        float4 v = __ldg(&XL4[(size_t)s * 32 + lane]);
        acc.x += w * v.x; acc.y += w * v.y; acc.z += w * v.z; acc.w += w * v.w;
    }
    float4 b = bg4[lane];
    float4 o;
    o.x = fmaxf(acc.x + b.x, 0.f); o.y = fmaxf(acc.y + b.y, 0.f);
    o.z = fmaxf(acc.z + b.z, 0.f); o.w = fmaxf(acc.w + b.w, 0.f);
    Out4[(size_t)node * 32 + lane] = o;
}

// ---------------- GCN2 beta-combine: y = relu((1-beta)*h + beta*m), float4 ----------------
__global__ void k_combine4(const float4* __restrict__ H, const float4* __restrict__ Mm,
                           float4* __restrict__ Out, int n4) {
    int i = blockIdx.x * 256 + threadIdx.x;
    if (i < n4) {
        float4 h = __ldg(&H[i]);
        float4 m = __ldg(&Mm[i]);
        float4 o;
        o.x = fmaxf((1.f - BETA_C) * h.x + BETA_C * m.x, 0.f);
        o.y = fmaxf((1.f - BETA_C) * h.y + BETA_C * m.y, 0.f);
        o.z = fmaxf((1.f - BETA_C) * h.z + BETA_C * m.z, 0.f);
        o.w = fmaxf((1.f - BETA_C) * h.w + BETA_C * m.w, 0.f);
        Out[i] = o;
    }
}

// ---------------- launcher ----------------
static inline void gemm(const float* A, const float* W, float* C, int M, int K, int Ncol) {
    if (Ncol >= 128) {
        dim3 g((Ncol + 127) / 128, (M + 127) / 128);
        k_gemm128<<<g, 256>>>(A, W, C, M, K, Ncol);
    } else {
        dim3 g((Ncol + 63) / 64, (M + 63) / 64);
        k_gemm<<<g, 256>>>(A, W, C, M, K, Ncol);
    }
}

extern "C" void kernel_launch(void* const* d_in, const int* in_sizes, int n_in,
                              void* d_out, int out_size) {
    const float* x   = (const float*)d_in[0];
    const void*  ei  = d_in[1];
    const float* W1  = (const float*)d_in[2];   const float* b1 = (const float*)d_in[3];
    const float* W2  = (const float*)d_in[4];   const float* b2 = (const float*)d_in[5];
    const float* W3  = (const float*)d_in[6];   const float* b3 = (const float*)d_in[7];
    const float* W4  = (const float*)d_in[8];   const float* b4 = (const float*)d_in[9];
    const float* Wl  = (const float*)d_in[10];  const float* Wr = (const float*)d_in[11];
    const float* att = (const float*)d_in[12];  const float* bg = (const float*)d_in[13];
    const float* Wc1 = (const float*)d_in[14];
    const float* W5  = (const float*)d_in[15];  const float* b5 = (const float*)d_in[16];
    const float* Wc2 = (const float*)d_in[17];
    const float* Wo  = (const float*)d_in[18];  const float* bo = (const float*)d_in[19];
    float* out = (float*)d_out;

    float *bufA, *bufB, *bufC, *X1, *X2;
    cudaGetSymbolAddress((void**)&bufA, g_bufA);
    cudaGetSymbolAddress((void**)&bufB, g_bufB);
    cudaGetSymbolAddress((void**)&bufC, g_bufC);
    cudaGetSymbolAddress((void**)&X1,   g_X1);
    cudaGetSymbolAddress((void**)&X2,   g_X2);

    const int nblkN  = (NN + 255) / 256;
    const int nblkE  = (EE + 255) / 256;
    const int nblkE2 = (EE2 + 255) / 256;
    const int nblkScan = (NN + 1023) / 1024;
    const int nblkNode = (NN + 7) / 8;        // 8 warps/block, warp per node

    // --- graph preprocessing ---
    k_detect<<<1, 32>>>((const int*)ei);
    k_convert<<<nblkE, 256>>>(ei);
    k_init_cnt<<<nblkN, 256>>>();
    k_count<<<nblkE, 256>>>();
    k_dinv<<<nblkN, 256>>>();
    k_scan1<<<nblkScan, 1024>>>();
    k_scan2<<<1, 32>>>(nblkScan);
    k_scan3<<<nblkScan, 1024>>>();
    k_fill<<<nblkE2, 256>>>();

    // --- layer 1: x1 = relu(prop(x @ W1) + b1)  [N,256] ---
    gemm(x, W1, bufA, NN, 300, 256);
    k_prop4<2, 0><<<nblkNode, 256>>>((const float4*)bufA, (float4*)X1, (const float4*)b1, nullptr);

    // --- layer 2: x2 = relu(prop(x1 @ W2) + b2)  [N,128] ---
    gemm(X1, W2, bufA, NN, 256, 128);
    k_prop4<1, 0><<<nblkNode, 256>>>((const float4*)bufA, (float4*)X2, (const float4*)b2, nullptr);

    // --- layer 3: h = relu(prop(x2 @ W3) + b3)  [N,64] ---
    gemm(X2, W3, bufA, NN, 128, 64);
    k_prop<2, 0><<<nblkNode, 256>>>(bufA, bufB, b3, nullptr);

    // --- layer 4: h4 = relu(prop(h @ W4) + b4)  [N,32] ---
    gemm(bufB, W4, bufA, NN, 64, 32);
    k_prop<1, 0><<<nblkNode, 256>>>(bufA, bufB, b4, nullptr);   // h4 in bufB

    // --- GATv2: xl = h4@Wl, xr = h4@Wr, softmax-attention, relu(+bg) ---
    gemm(bufB, Wl, bufA, NN, 32, 128);   // xl
    gemm(bufB, Wr, bufC, NN, 32, 128);   // xr
    k_gat_logits<<<nblkNode, 256>>>((const float4*)bufA, (const float4*)bufC, att);
    k_gat_aggr<<<nblkNode, 256>>>((const float4*)bufA, (float4*)bufB, (const float4*)bg);

    // --- GCN2 #1 (x0 = x2, Wc1) ---
    k_prop4<1, 2><<<nblkNode, 256>>>((const float4*)bufB, (float4*)bufA, nullptr, (const float4*)X2);
    gemm(bufA, Wc1, bufC, NN, 128, 128);
    k_combine4<<<(NN * 32 + 255) / 256, 256>>>((const float4*)bufA, (const float4*)bufC,
                                               (float4*)bufB, NN * 32);

    // --- layer 5: relu(prop(h @ W5) + b5)  [N,256] ---
    gemm(bufB, W5, bufA, NN, 128, 256);
    k_prop4<2, 0><<<nblkNode, 256>>>((const float4*)bufA, (float4*)bufB, (const float4*)b5, nullptr);

    // --- GCN2 #2 (x0 = x1, Wc2) ---
    k_prop4<2, 2><<<nblkNode, 256>>>((const float4*)bufB, (float4*)bufA, nullptr, (const float4*)X1);
    gemm(bufA, Wc2, bufC, NN, 256, 256);
    k_combine4<<<(NN * 64 + 255) / 256, 256>>>((const float4*)bufA, (const float4*)bufC,
                                               (float4*)bufB, NN * 64);

    // --- output: prop(h @ Wo) + bo  [N,128] ---
    gemm(bufB, Wo, bufA, NN, 256, 128);
    k_prop4<1, 1><<<nblkNode, 256>>>((const float4*)bufA, (float4*)out, (const float4*)bo, nullptr);
}

// round 10
// speedup vs baseline: 1.0854x; 1.0854x over previous
#include <cuda_runtime.h>
#include <math.h>
#include <stdint.h>

#define NN   50000
#define EE   800000
#define EE2  (EE + NN)        // 850000 edges incl self-loops
#define BETA_C  0.04879016416943205f   // log(0.1/2 + 1)

// ---------------- device scratch (static; no allocation allowed) ----------------
__device__ __align__(16) float g_bufA[NN * 256];
__device__ __align__(16) float g_bufB[NN * 256];
__device__ __align__(16) float g_bufC[NN * 256];
__device__ __align__(16) float g_X1[NN * 256];
__device__ __align__(16) float g_X2[NN * 128];
__device__ float g_dinv[NN];
__device__ int   g_cnt[NN];
__device__ int   g_rowptr[NN + 1];
__device__ int   g_src[EE];
__device__ int   g_dst[EE];
__device__ __align__(8) int2 g_csr[EE2];      // packed {src, norm-bits}
__device__ __align__(16) float g_alog[EE2 * 4];
__device__ int   g_part[64];
__device__ int   g_is64;

// ---------------- edge dtype detection & conversion ----------------
__global__ void k_detect(const int* __restrict__ ei) {
    if (threadIdx.x == 0 && blockIdx.x == 0) {
        int flag64 = 1;
        for (int i = 1; i < 2048; i += 2) {
            if (ei[i] != 0) { flag64 = 0; break; }
        }
        g_is64 = flag64;
    }
}

__global__ void k_convert(const void* __restrict__ ei) {
    int e = blockIdx.x * 256 + threadIdx.x;
    if (e >= EE) return;
    if (g_is64) {
        const long long* p = (const long long*)ei;
        g_src[e] = (int)p[e];
        g_dst[e] = (int)p[EE + e];
    } else {
        const int* p = (const int*)ei;
        g_src[e] = p[e];
        g_dst[e] = p[EE + e];
    }
}

// ---------------- degree / norm / CSR build ----------------
__global__ void k_init_cnt() {
    int i = blockIdx.x * 256 + threadIdx.x;
    if (i < NN) g_cnt[i] = 1;   // self-loop contributes 1 to in-degree
}

__global__ void k_count() {
    int e = blockIdx.x * 256 + threadIdx.x;
    if (e < EE) atomicAdd(&g_cnt[g_dst[e]], 1);
}

__global__ void k_dinv() {
    int i = blockIdx.x * 256 + threadIdx.x;
    if (i < NN) {
        float d = (float)g_cnt[i];
        g_dinv[i] = (d > 0.f) ? rsqrtf(d) : 0.f;
    }
}

// exclusive scan of g_cnt -> g_rowptr (three-phase)
__global__ void k_scan1() {
    __shared__ int sh[1024];
    int i = blockIdx.x * 1024 + threadIdx.x;
    int v = (i < NN) ? g_cnt[i] : 0;
    sh[threadIdx.x] = v;
    __syncthreads();
    for (int off = 1; off < 1024; off <<= 1) {
        int t = (threadIdx.x >= off) ? sh[threadIdx.x - off] : 0;
        __syncthreads();
        sh[threadIdx.x] += t;
        __syncthreads();
    }
    if (i < NN) g_rowptr[i] = sh[threadIdx.x] - v;   // exclusive
    if (threadIdx.x == 1023) g_part[blockIdx.x] = sh[1023];
}

__global__ void k_scan2(int nblk) {
    if (threadIdx.x == 0 && blockIdx.x == 0) {
        int acc = 0;
        for (int b = 0; b < nblk; b++) { int t = g_part[b]; g_part[b] = acc; acc += t; }
    }
}

__global__ void k_scan3() {
    int i = blockIdx.x * 1024 + threadIdx.x;
    if (i < NN) {
        g_rowptr[i] += g_part[blockIdx.x];
        g_cnt[i] = 0;    // reuse as fill cursor
    }
    if (i == 0) g_rowptr[NN] = EE2;
}

__global__ void k_fill() {
    int e = blockIdx.x * 256 + threadIdx.x;
    if (e >= EE2) return;
    int s, d;
    if (e < EE) { s = g_src[e]; d = g_dst[e]; }
    else        { s = d = e - EE; }
    float nrm = g_dinv[s] * g_dinv[d];
    int pos = g_rowptr[d] + atomicAdd(&g_cnt[d], 1);
    g_csr[pos] = make_int2(s, __float_as_int(nrm));
}

// ---------------- fp32 tiled GEMM 64x64 (small-N fallback, Ncol=32) ----------------
__global__ void k_gemm(const float* __restrict__ A, const float* __restrict__ W,
                       float* __restrict__ C, int M, int K, int Ncol) {
    __shared__ float As[64][17];
    __shared__ float Ws[16][64];
    int tx = threadIdx.x & 15, ty = threadIdx.x >> 4;
    int rb = blockIdx.y * 64, cb = blockIdx.x * 64;
    float acc[4][4] = {};

    for (int k0 = 0; k0 < K; k0 += 16) {
#pragma unroll
        for (int l = 0; l < 4; l++) {
            int lin = threadIdx.x + l * 256;
            int m = lin >> 4, kk = lin & 15;
            int gr = rb + m, gk = k0 + kk;
            As[m][kk] = (gr < M && gk < K) ? A[(size_t)gr * K + gk] : 0.f;
        }
#pragma unroll
        for (int l = 0; l < 4; l++) {
            int lin = threadIdx.x + l * 256;
            int kk = lin >> 6, n = lin & 63;
            int gk = k0 + kk, gc = cb + n;
            Ws[kk][n] = (gk < K && gc < Ncol) ? W[(size_t)gk * Ncol + gc] : 0.f;
        }
        __syncthreads();
#pragma unroll
        for (int kk = 0; kk < 16; kk++) {
            float a[4], b[4];
#pragma unroll
            for (int i = 0; i < 4; i++) a[i] = As[ty + i * 16][kk];
#pragma unroll
            for (int j = 0; j < 4; j++) b[j] = Ws[kk][tx + j * 16];
#pragma unroll
            for (int i = 0; i < 4; i++)
#pragma unroll
                for (int j = 0; j < 4; j++) acc[i][j] += a[i] * b[j];
        }
        __syncthreads();
    }
#pragma unroll
    for (int i = 0; i < 4; i++) {
        int r = rb + ty + i * 16;
        if (r >= M) continue;
#pragma unroll
        for (int j = 0; j < 4; j++) {
            int c = cb + tx + j * 16;
            if (c < Ncol) C[(size_t)r * Ncol + c] = acc[i][j];
        }
    }
}

// ---------------- 3xTF32 tensor-core GEMM 128x128x8 (fp32-accurate) ----------------
__device__ __forceinline__ uint32_t f2tf(float x) {
    uint32_t r;
    asm("cvt.rna.tf32.f32 %0, %1;" : "=r"(r) : "f"(x));
    return r;
}

__device__ __forceinline__ void split_tf(float x, uint32_t& hi, uint32_t& lo) {
    hi = f2tf(x);
    float hf = __uint_as_float(hi);
    lo = f2tf(x - hf);
}

__device__ __forceinline__ float4 ld4_guard(const float* __restrict__ p, int row, int col,
                                            int nrow, int ncol, int pitch) {
    float4 v = make_float4(0.f, 0.f, 0.f, 0.f);
    if (row < nrow) {
        const float* q = p + (size_t)row * pitch + col;
        if (col + 3 < ncol) v = *(const float4*)q;
        else {
            if (col     < ncol) v.x = q[0];
            if (col + 1 < ncol) v.y = q[1];
            if (col + 2 < ncol) v.z = q[2];
            if (col + 3 < ncol) v.w = q[3];
        }
    }
    return v;
}

#define MMA_TF32(c, a0,a1,a2,a3, b0,b1)                                        \
    asm volatile(                                                              \
        "mma.sync.aligned.m16n8k8.row.col.f32.tf32.tf32.f32 "                  \
        "{%0,%1,%2,%3}, {%4,%5,%6,%7}, {%8,%9}, {%0,%1,%2,%3};"                \
        : "+f"(c[0]), "+f"(c[1]), "+f"(c[2]), "+f"(c[3])                       \
        : "r"(a0), "r"(a1), "r"(a2), "r"(a3), "r"(b0), "r"(b1))

__global__ void __launch_bounds__(256, 2)
k_gemm_tf32x3(const float* __restrict__ A, const float* __restrict__ W,
              float* __restrict__ C, int M, int K, int Ncol) {
    __shared__ uint32_t AsH[2][8][132];   // [k][m] hi bits, pitch 132
    __shared__ uint32_t AsL[2][8][132];   // [k][m] lo bits
    __shared__ uint32_t WsH[2][8][132];   // [k][n] hi bits
    __shared__ uint32_t WsL[2][8][132];   // [k][n] lo bits
    int tid = threadIdx.x;
    int lane = tid & 31, w = tid >> 5;
    int gid = lane >> 2, tig = lane & 3;
    int wm = (w & 1) * 64, wn = (w >> 1) * 32;
    int rb = blockIdx.y * 128, cb = blockIdx.x * 128;

    float cfr[16][4];
#pragma unroll
    for (int i = 0; i < 16; i++) { cfr[i][0] = cfr[i][1] = cfr[i][2] = cfr[i][3] = 0.f; }

    // staging coords: A tile 128 rows x 8 k (1 float4/thread), W tile 8 k x 128 n
    int aRow = tid >> 1, aKc = (tid & 1) * 4;
    int wKr = tid >> 5, wNc = (tid & 31) * 4;

    // preload tile 0 into buffer 0
    {
        float4 va = ld4_guard(A, rb + aRow, aKc, M, K, K);
        float4 vw = ld4_guard(W, wKr, cb + wNc, K, Ncol, Ncol);
        uint32_t h, l;
        split_tf(va.x, h, l); AsH[0][aKc + 0][aRow] = h; AsL[0][aKc + 0][aRow] = l;
        split_tf(va.y, h, l); AsH[0][aKc + 1][aRow] = h; AsL[0][aKc + 1][aRow] = l;
        split_tf(va.z, h, l); AsH[0][aKc + 2][aRow] = h; AsL[0][aKc + 2][aRow] = l;
        split_tf(va.w, h, l); AsH[0][aKc + 3][aRow] = h; AsL[0][aKc + 3][aRow] = l;
        uint4 th, tl;
        split_tf(vw.x, th.x, tl.x); split_tf(vw.y, th.y, tl.y);
        split_tf(vw.z, th.z, tl.z); split_tf(vw.w, th.w, tl.w);
        *(uint4*)&WsH[0][wKr][wNc] = th;
        *(uint4*)&WsL[0][wKr][wNc] = tl;
    }
    __syncthreads();

    int nT = (K + 7) >> 3;
    for (int t = 0; t < nT; t++) {
        int cur = t & 1, nxt = cur ^ 1;
        float4 sa, sw;
        if (t + 1 < nT) {
            int k0 = (t + 1) << 3;
            sa = ld4_guard(A, rb + aRow, k0 + aKc, M, K, K);
            sw = ld4_guard(W, k0 + wKr, cb + wNc, K, Ncol, Ncol);
        }

        // B fragments (hi+lo) for 4 n-tiles
        uint32_t bh[4][2], bl[4][2];
#pragma unroll
        for (int nt = 0; nt < 4; nt++) {
            int n = wn + nt * 8 + gid;
            bh[nt][0] = WsH[cur][tig][n];     bh[nt][1] = WsH[cur][4 + tig][n];
            bl[nt][0] = WsL[cur][tig][n];     bl[nt][1] = WsL[cur][4 + tig][n];
        }
#pragma unroll
        for (int mt = 0; mt < 4; mt++) {
            int m = wm + mt * 16 + gid;
            uint32_t ah0 = AsH[cur][tig][m],     ah1 = AsH[cur][tig][m + 8];
            uint32_t ah2 = AsH[cur][4 + tig][m], ah3 = AsH[cur][4 + tig][m + 8];
            uint32_t al0 = AsL[cur][tig][m],     al1 = AsL[cur][tig][m + 8];
            uint32_t al2 = AsL[cur][4 + tig][m], al3 = AsL[cur][4 + tig][m + 8];
#pragma unroll
            for (int nt = 0; nt < 4; nt++) {
                float* c = cfr[mt * 4 + nt];
                MMA_TF32(c, al0, al1, al2, al3, bh[nt][0], bh[nt][1]);   // lo*hi
                MMA_TF32(c, ah0, ah1, ah2, ah3, bl[nt][0], bl[nt][1]);   // hi*lo
                MMA_TF32(c, ah0, ah1, ah2, ah3, bh[nt][0], bh[nt][1]);   // hi*hi
            }
        }

        if (t + 1 < nT) {
            uint32_t h, l;
            split_tf(sa.x, h, l); AsH[nxt][aKc + 0][aRow] = h; AsL[nxt][aKc + 0][aRow] = l;
            split_tf(sa.y, h, l); AsH[nxt][aKc + 1][aRow] = h; AsL[nxt][aKc + 1][aRow] = l;
            split_tf(sa.z, h, l); AsH[nxt][aKc + 2][aRow] = h; AsL[nxt][aKc + 2][aRow] = l;
            split_tf(sa.w, h, l); AsH[nxt][aKc + 3][aRow] = h; AsL[nxt][aKc + 3][aRow] = l;
            uint4 th, tl;
            split_tf(sw.x, th.x, tl.x); split_tf(sw.y, th.y, tl.y);
            split_tf(sw.z, th.z, tl.z); split_tf(sw.w, th.w, tl.w);
            *(uint4*)&WsH[nxt][wKr][wNc] = th;
            *(uint4*)&WsL[nxt][wKr][wNc] = tl;
            __syncthreads();
        }
    }

    // epilogue: C fragments -> gmem (float2 stores, Ncol even)
#pragma unroll
    for (int mt = 0; mt < 4; mt++) {
        int r0 = rb + wm + mt * 16 + gid;
        int r1 = r0 + 8;
#pragma unroll
        for (int nt = 0; nt < 4; nt++) {
            int c0 = cb + wn + nt * 8 + tig * 2;
            float* cf = cfr[mt * 4 + nt];
            if (c0 < Ncol) {
                if (r0 < M) *(float2*)&C[(size_t)r0 * Ncol + c0] = make_float2(cf[0], cf[1]);
                if (r1 < M) *(float2*)&C[(size_t)r1 * Ncol + c0] = make_float2(cf[2], cf[3]);
            }
        }
    }
}

// ---------------- CSR gather-propagation (scalar, D = C*32) ----------------
// MODE 0: relu(acc+bias)   MODE 1: acc+bias   MODE 2: 0.5*acc + 0.5*X0
template <int C, int MODE>
__global__ void k_prop(const float* __restrict__ H, float* __restrict__ Out,
                       const float* __restrict__ bias, const float* __restrict__ X0) {
    int warp = threadIdx.x >> 5, lane = threadIdx.x & 31;
    int node = blockIdx.x * 8 + warp;
    if (node >= NN) return;
    const int D = C * 32;
    int rs = g_rowptr[node], re = g_rowptr[node + 1];
    float acc[C];
#pragma unroll
    for (int c = 0; c < C; c++) acc[c] = 0.f;

#pragma unroll 4
    for (int k = rs; k < re; k++) {
        int2 e = g_csr[k];
        int s = e.x;
        float w = __int_as_float(e.y);
        const float* hp = H + (size_t)s * D + lane;
#pragma unroll
        for (int c = 0; c < C; c++) acc[c] += w * __ldg(hp + 32 * c);
    }
    float* op = Out + (size_t)node * D + lane;
#pragma unroll
    for (int c = 0; c < C; c++) {
        float v = acc[c];
        if (MODE == 0)      { v += bias[lane + 32 * c]; v = fmaxf(v, 0.f); }
        else if (MODE == 1) { v += bias[lane + 32 * c]; }
        else                { v = 0.5f * v + 0.5f * X0[(size_t)node * D + lane + 32 * c]; }
        op[32 * c] = v;
    }
}

// ---------------- CSR gather-propagation (float4, D = C4*128) ----------------
template <int C4, int MODE>
__global__ void k_prop4(const float4* __restrict__ H4, float4* __restrict__ Out4,
                        const float4* __restrict__ bias4, const float4* __restrict__ X04) {
    int warp = threadIdx.x >> 5, lane = threadIdx.x & 31;
    int node = blockIdx.x * 8 + warp;
    if (node >= NN) return;
    const int D4 = C4 * 32;            // float4s per row
    int rs = g_rowptr[node], re = g_rowptr[node + 1];
    float4 acc[C4];
#pragma unroll
    for (int c = 0; c < C4; c++) acc[c] = make_float4(0.f, 0.f, 0.f, 0.f);

#pragma unroll 4
    for (int k = rs; k < re; k++) {
        int2 e = g_csr[k];
        int s = e.x;
        float w = __int_as_float(e.y);
        const float4* hp = H4 + (size_t)s * D4 + lane;
#pragma unroll
        for (int c = 0; c < C4; c++) {
            float4 v = __ldg(hp + 32 * c);
            acc[c].x += w * v.x; acc[c].y += w * v.y;
            acc[c].z += w * v.z; acc[c].w += w * v.w;
        }
    }
    float4* op = Out4 + (size_t)node * D4 + lane;
#pragma unroll
    for (int c = 0; c < C4; c++) {
        float4 v = acc[c];
        if (MODE == 0) {
            float4 b = bias4[lane + 32 * c];
            v.x = fmaxf(v.x + b.x, 0.f); v.y = fmaxf(v.y + b.y, 0.f);
            v.z = fmaxf(v.z + b.z, 0.f); v.w = fmaxf(v.w + b.w, 0.f);
        } else if (MODE == 1) {
            float4 b = bias4[lane + 32 * c];
            v.x += b.x; v.y += b.y; v.z += b.z; v.w += b.w;
        } else {
            float4 x0 = X04[(size_t)node * D4 + lane + 32 * c];
            v.x = 0.5f * v.x + 0.5f * x0.x; v.y = 0.5f * v.y + 0.5f * x0.y;
            v.z = 0.5f * v.z + 0.5f * x0.z; v.w = 0.5f * v.w + 0.5f * x0.w;
        }
        op[32 * c] = v;
    }
}

// ---------------- GATv2 ----------------
__global__ void k_gat_logits(const float4* __restrict__ XL4, const float4* __restrict__ XR4,
                             const float* __restrict__ att) {
    int warp = threadIdx.x >> 5, lane = threadIdx.x & 31;
    int node = blockIdx.x * 8 + warp;
    if (node >= NN) return;
    int rs = g_rowptr[node], re = g_rowptr[node + 1];
    float4 xr = XR4[(size_t)node * 32 + lane];
    float4 at = ((const float4*)att)[lane];

#pragma unroll 2
    for (int pos = rs; pos < re; pos++) {
        int s = g_csr[pos].x;
        float4 xl = __ldg(&XL4[(size_t)s * 32 + lane]);
        float v0 = xl.x + xr.x; v0 = v0 > 0.f ? v0 : 0.2f * v0;
        float v1 = xl.y + xr.y; v1 = v1 > 0.f ? v1 : 0.2f * v1;
        float v2 = xl.z + xr.z; v2 = v2 > 0.f ? v2 : 0.2f * v2;
        float v3 = xl.w + xr.w; v3 = v3 > 0.f ? v3 : 0.2f * v3;
        float sum = at.x * v0 + at.y * v1 + at.z * v2 + at.w * v3;
        sum += __shfl_xor_sync(0xFFFFFFFFu, sum, 1);
        sum += __shfl_xor_sync(0xFFFFFFFFu, sum, 2);
        sum += __shfl_xor_sync(0xFFFFFFFFu, sum, 4);
        if ((lane & 7) == 0) g_alog[(size_t)pos * 4 + (lane >> 3)] = sum;
    }
}

__global__ void k_gat_aggr(const float4* __restrict__ XL4, float4* __restrict__ Out4,
                           const float4* __restrict__ bg4) {
    int warp = threadIdx.x >> 5, lane = threadIdx.x & 31;
    int node = blockIdx.x * 8 + warp;
    if (node >= NN) return;
    int rs = g_rowptr[node], re = g_rowptr[node + 1];
    const float4* AL4 = (const float4*)g_alog;

    float4 mx = make_float4(-1e30f, -1e30f, -1e30f, -1e30f);
    for (int pos = rs + lane; pos < re; pos += 32) {
        float4 a = AL4[pos];
        mx.x = fmaxf(mx.x, a.x); mx.y = fmaxf(mx.y, a.y);
        mx.z = fmaxf(mx.z, a.z); mx.w = fmaxf(mx.w, a.w);
    }
#pragma unroll
    for (int off = 16; off; off >>= 1) {
        mx.x = fmaxf(mx.x, __shfl_xor_sync(0xFFFFFFFFu, mx.x, off));
        mx.y = fmaxf(mx.y, __shfl_xor_sync(0xFFFFFFFFu, mx.y, off));
        mx.z = fmaxf(mx.z, __shfl_xor_sync(0xFFFFFFFFu, mx.z, off));
        mx.w = fmaxf(mx.w, __shfl_xor_sync(0xFFFFFFFFu, mx.w, off));
    }
    float4 se = make_float4(0.f, 0.f, 0.f, 0.f);
    for (int pos = rs + lane; pos < re; pos += 32) {
        float4 a = AL4[pos];
        se.x += __expf(a.x - mx.x); se.y += __expf(a.y - mx.y);
        se.z += __expf(a.z - mx.z); se.w += __expf(a.w - mx.w);
    }
#pragma unroll
    for (int off = 16; off; off >>= 1) {
        se.x += __shfl_xor_sync(0xFFFFFFFFu, se.x, off);
        se.y += __shfl_xor_sync(0xFFFFFFFFu, se.y, off);
        se.z += __shfl_xor_sync(0xFFFFFFFFu, se.z, off);
        se.w += __shfl_xor_sync(0xFFFFFFFFu, se.w, off);
    }
    int head = lane >> 3;
    float mxh  = (head == 0) ? mx.x : (head == 1) ? mx.y : (head == 2) ? mx.z : mx.w;
    float seh  = (head == 0) ? se.x : (head == 1) ? se.y : (head == 2) ? se.z : se.w;
    float invh = 1.f / (seh + 1e-16f);

    float4 acc = make_float4(0.f, 0.f, 0.f, 0.f);
#pragma unroll 2
    for (int pos = rs; pos < re; pos++) {
        float4 a = AL4[pos];    // broadcast across warp
        float ah = (head == 0) ? a.x : (head == 1) ? a.y : (head == 2) ? a.z : a.w;
        float w = __expf(ah - mxh) * invh;
        int s = g_csr[pos].x;
        float4 v = __ldg(&XL4[(size_t)s * 32 + lane]);
        acc.x += w * v.x; acc.y += w * v.y; acc.z += w * v.z; acc.w += w * v.w;
    }
    float4 b = bg4[lane];
    float4 o;
    o.x = fmaxf(acc.x + b.x, 0.f); o.y = fmaxf(acc.y + b.y, 0.f);
    o.z = fmaxf(acc.z + b.z, 0.f); o.w = fmaxf(acc.w + b.w, 0.f);
    Out4[(size_t)node * 32 + lane] = o;
}

// ---------------- GCN2 beta-combine: y = relu((1-beta)*h + beta*m), float4 ----------------
__global__ void k_combine4(const float4* __restrict__ H, const float4* __restrict__ Mm,
                           float4* __restrict__ Out, int n4) {
    int i = blockIdx.x * 256 + threadIdx.x;
    if (i < n4) {
        float4 h = __ldg(&H[i]);
        float4 m = __ldg(&Mm[i]);
        float4 o;
        o.x = fmaxf((1.f - BETA_C) * h.x + BETA_C * m.x, 0.f);
        o.y = fmaxf((1.f - BETA_C) * h.y + BETA_C * m.y, 0.f);
        o.z = fmaxf((1.f - BETA_C) * h.z + BETA_C * m.z, 0.f);
        o.w = fmaxf((1.f - BETA_C) * h.w + BETA_C * m.w, 0.f);
        Out[i] = o;
    }
}

// ---------------- launcher ----------------
static inline void gemm(const float* A, const float* W, float* C, int M, int K, int Ncol) {
    if (Ncol >= 64) {
        dim3 g((Ncol + 127) / 128, (M + 127) / 128);
        k_gemm_tf32x3<<<g, 256>>>(A, W, C, M, K, Ncol);
    } else {
        dim3 g((Ncol + 63) / 64, (M + 63) / 64);
        k_gemm<<<g, 256>>>(A, W, C, M, K, Ncol);
    }
}

extern "C" void kernel_launch(void* const* d_in, const int* in_sizes, int n_in,
                              void* d_out, int out_size) {
    const float* x   = (const float*)d_in[0];
    const void*  ei  = d_in[1];
    const float* W1  = (const float*)d_in[2];   const float* b1 = (const float*)d_in[3];
    const float* W2  = (const float*)d_in[4];   const float* b2 = (const float*)d_in[5];
    const float* W3  = (const float*)d_in[6];   const float* b3 = (const float*)d_in[7];
    const float* W4  = (const float*)d_in[8];   const float* b4 = (const float*)d_in[9];
    const float* Wl  = (const float*)d_in[10];  const float* Wr = (const float*)d_in[11];
    const float* att = (const float*)d_in[12];  const float* bg = (const float*)d_in[13];
    const float* Wc1 = (const float*)d_in[14];
    const float* W5  = (const float*)d_in[15];  const float* b5 = (const float*)d_in[16];
    const float* Wc2 = (const float*)d_in[17];
    const float* Wo  = (const float*)d_in[18];  const float* bo = (const float*)d_in[19];
    float* out = (float*)d_out;

    float *bufA, *bufB, *bufC, *X1, *X2;
    cudaGetSymbolAddress((void**)&bufA, g_bufA);
    cudaGetSymbolAddress((void**)&bufB, g_bufB);
    cudaGetSymbolAddress((void**)&bufC, g_bufC);
    cudaGetSymbolAddress((void**)&X1,   g_X1);
    cudaGetSymbolAddress((void**)&X2,   g_X2);

    const int nblkN  = (NN + 255) / 256;
    const int nblkE  = (EE + 255) / 256;
    const int nblkE2 = (EE2 + 255) / 256;
    const int nblkScan = (NN + 1023) / 1024;
    const int nblkNode = (NN + 7) / 8;        // 8 warps/block, warp per node

    // --- graph preprocessing ---
    k_detect<<<1, 32>>>((const int*)ei);
    k_convert<<<nblkE, 256>>>(ei);
    k_init_cnt<<<nblkN, 256>>>();
    k_count<<<nblkE, 256>>>();
    k_dinv<<<nblkN, 256>>>();
    k_scan1<<<nblkScan, 1024>>>();
    k_scan2<<<1, 32>>>(nblkScan);
    k_scan3<<<nblkScan, 1024>>>();
    k_fill<<<nblkE2, 256>>>();

    // --- layer 1: x1 = relu(prop(x @ W1) + b1)  [N,256] ---
    gemm(x, W1, bufA, NN, 300, 256);
    k_prop4<2, 0><<<nblkNode, 256>>>((const float4*)bufA, (float4*)X1, (const float4*)b1, nullptr);

    // --- layer 2: x2 = relu(prop(x1 @ W2) + b2)  [N,128] ---
    gemm(X1, W2, bufA, NN, 256, 128);
    k_prop4<1, 0><<<nblkNode, 256>>>((const float4*)bufA, (float4*)X2, (const float4*)b2, nullptr);

    // --- layer 3: h = relu(prop(x2 @ W3) + b3)  [N,64] ---
    gemm(X2, W3, bufA, NN, 128, 64);
    k_prop<2, 0><<<nblkNode, 256>>>(bufA, bufB, b3, nullptr);

    // --- layer 4: h4 = relu(prop(h @ W4) + b4)  [N,32] ---
    gemm(bufB, W4, bufA, NN, 64, 32);
    k_prop<1, 0><<<nblkNode, 256>>>(bufA, bufB, b4, nullptr);   // h4 in bufB

    // --- GATv2: xl = h4@Wl, xr = h4@Wr, softmax-attention, relu(+bg) ---
    gemm(bufB, Wl, bufA, NN, 32, 128);   // xl
    gemm(bufB, Wr, bufC, NN, 32, 128);   // xr
    k_gat_logits<<<nblkNode, 256>>>((const float4*)bufA, (const float4*)bufC, att);
    k_gat_aggr<<<nblkNode, 256>>>((const float4*)bufA, (float4*)bufB, (const float4*)bg);

    // --- GCN2 #1 (x0 = x2, Wc1) ---
    k_prop4<1, 2><<<nblkNode, 256>>>((const float4*)bufB, (float4*)bufA, nullptr, (const float4*)X2);
    gemm(bufA, Wc1, bufC, NN, 128, 128);
    k_combine4<<<(NN * 32 + 255) / 256, 256>>>((const float4*)bufA, (const float4*)bufC,
                                               (float4*)bufB, NN * 32);

    // --- layer 5: relu(prop(h @ W5) + b5)  [N,256] ---
    gemm(bufB, W5, bufA, NN, 128, 256);
    k_prop4<2, 0><<<nblkNode, 256>>>((const float4*)bufA, (float4*)bufB, (const float4*)b5, nullptr);

    // --- GCN2 #2 (x0 = x1, Wc2) ---
    k_prop4<2, 2><<<nblkNode, 256>>>((const float4*)bufB, (float4*)bufA, nullptr, (const float4*)X1);
    gemm(bufA, Wc2, bufC, NN, 256, 256);
    k_combine4<<<(NN * 64 + 255) / 256, 256>>>((const float4*)bufA, (const float4*)bufC,
                                               (float4*)bufB, NN * 64);

    // --- output: prop(h @ Wo) + bo  [N,128] ---
    gemm(bufB, Wo, bufA, NN, 256, 128);
    k_prop4<1, 1><<<nblkNode, 256>>>((const float4*)bufA, (float4*)out, (const float4*)bo, nullptr);
}